// round 11
// baseline (speedup 1.0000x reference)
#include <cuda_runtime.h>
#include <cstdint>

// Problem constants (fixed shapes per reference)
#define BATCH 4
#define NNODES 4096          // N
#define CH 96                // C
#define N1 (NNODES + 1)      // 4097
#define PS 4                 // pooling_patch_size
#define NPATCH (NNODES / PS) // 1024
// tk = ps / reduction_ratio = 1

// Scratch: v[b][m] = sum_c sigmoid(nodes[b,m,c]) * theta[c]
__device__ float g_v[BATCH * NNODES];

__device__ __forceinline__ float fsig(float x) {
    // fast sigmoid: ~1e-7 rel err (EX2 + RCP on MUFU)
    return __fdividef(1.0f, 1.0f + __expf(-x));
}

// Kernel 1: v[b,m] = dot(sigmoid(x[b,1+m,:]), theta).
// 512 blocks x 256 threads, 4 independent rows per warp. Triggers programmatic
// launch completion IMMEDIATELY so kernel 2's blocks co-reside and prefetch.
__global__ __launch_bounds__(256) void node_score_kernel(
    const float* __restrict__ x, const float* __restrict__ theta,
    float* __restrict__ out)
{
    cudaTriggerProgrammaticLaunchCompletion();   // let kernel 2 place now

    const int tid  = threadIdx.x;
    const int lane = tid & 31;
    const int gw   = blockIdx.x * 8 + (tid >> 5);   // global warp id, 0..4095

    const float t0 = theta[lane];
    const float t1 = theta[lane + 32];
    const float t2 = theta[lane + 64];

    if (blockIdx.x == 0) {
        // CLS rows: 4*96 = 384 elements
        for (int i = tid; i < BATCH * CH; i += 256) {
            const int bb = i / CH, c = i % CH;
            out[(size_t)bb * (NPATCH + 1) * CH + c] = x[(size_t)bb * N1 * CH + c];
        }
    }

#pragma unroll
    for (int r = 0; r < 4; r++) {
        const int row = gw + r * 4096;              // 0..16383
        const int b = row >> 12;
        const int m = row & (NNODES - 1);
        const float* xr = x + ((size_t)b * N1 + 1 + m) * CH;
        float s = fsig(xr[lane])      * t0
                + fsig(xr[lane + 32]) * t1
                + fsig(xr[lane + 64]) * t2;
#pragma unroll
        for (int off = 16; off > 0; off >>= 1)
            s += __shfl_down_sync(0xffffffffu, s, off);
        if (lane == 0) g_v[row] = s;
    }
}

// Kernel 2 (R2 main-loop body — at the effective HBM ceiling; five variants all
// regressed). PDL version: prefetch iteration-0 edge slabs (independent of g_v)
// BEFORE the grid-dependency sync, consume v after.
// Reference quirk preserved: gathered node index is the WITHIN-PATCH offset.
__global__ __launch_bounds__(256) void score_pool_kernel(
    const float* __restrict__ edge, const float* __restrict__ x,
    float* __restrict__ out)
{
    __shared__ float red[8][4];
    __shared__ float s_scale;
    __shared__ int   s_bidx;

    const int pg = blockIdx.x;         // 0..4095
    const int b  = pg >> 10;
    const int p  = pg & (NPATCH - 1);
    const int tid  = threadIdx.x;
    const int lane = tid & 31;
    const int wid  = tid >> 5;

    const float4* e0 = (const float4*)(edge + ((size_t)(b << 12) + (p << 2)) * NNODES);
    // row stride in float4 units: 4096/4 = 1024

    // --- Pre-sync prefetch: iteration-0 slabs; edge does NOT depend on k1 ---
    const float4 p0 = e0[tid];
    const float4 p1 = e0[tid + 1024];
    const float4 p2 = e0[tid + 2048];
    const float4 p3 = e0[tid + 3072];

    // Wait for node_score_kernel's g_v to be complete & visible.
    cudaGridDependencySynchronize();

    const float4* vv4 = (const float4*)(g_v + (b << 12));

    // Iteration 0 from prefetched registers
    const float4 w0 = vv4[tid];
    float s0 = fsig(p0.x)*w0.x + fsig(p0.y)*w0.y + fsig(p0.z)*w0.z + fsig(p0.w)*w0.w;
    float s1 = fsig(p1.x)*w0.x + fsig(p1.y)*w0.y + fsig(p1.z)*w0.z + fsig(p1.w)*w0.w;
    float s2 = fsig(p2.x)*w0.x + fsig(p2.y)*w0.y + fsig(p2.z)*w0.z + fsig(p2.w)*w0.w;
    float s3 = fsig(p3.x)*w0.x + fsig(p3.y)*w0.y + fsig(p3.z)*w0.z + fsig(p3.w)*w0.w;

    // Iterations 1..3 (proven R2 body)
#pragma unroll
    for (int i = tid + 256; i < 1024; i += 256) {
        const float4 w  = vv4[i];
        const float4 a0 = e0[i];
        const float4 a1 = e0[i + 1024];
        const float4 a2 = e0[i + 2048];
        const float4 a3 = e0[i + 3072];
        s0 += fsig(a0.x)*w.x + fsig(a0.y)*w.y + fsig(a0.z)*w.z + fsig(a0.w)*w.w;
        s1 += fsig(a1.x)*w.x + fsig(a1.y)*w.y + fsig(a1.z)*w.z + fsig(a1.w)*w.w;
        s2 += fsig(a2.x)*w.x + fsig(a2.y)*w.y + fsig(a2.z)*w.z + fsig(a2.w)*w.w;
        s3 += fsig(a3.x)*w.x + fsig(a3.y)*w.y + fsig(a3.z)*w.z + fsig(a3.w)*w.w;
    }

#pragma unroll
    for (int off = 16; off > 0; off >>= 1) {
        s0 += __shfl_down_sync(0xffffffffu, s0, off);
        s1 += __shfl_down_sync(0xffffffffu, s1, off);
        s2 += __shfl_down_sync(0xffffffffu, s2, off);
        s3 += __shfl_down_sync(0xffffffffu, s3, off);
    }
    if (lane == 0) {
        red[wid][0] = s0; red[wid][1] = s1; red[wid][2] = s2; red[wid][3] = s3;
    }
    __syncthreads();

    if (tid == 0) {
        float sc[4];
#pragma unroll
        for (int r = 0; r < 4; r++) {
            float t = 0.f;
#pragma unroll
            for (int w = 0; w < 8; w++) t += red[w][r];
            sc[r] = t;
        }
        // top-1 with lowest-index tie-break (strict >)
        float best = sc[0]; int bi = 0;
#pragma unroll
        for (int r = 1; r < 4; r++)
            if (sc[r] > best) { best = sc[r]; bi = r; }
        s_scale = best + 1.0f;   // pooled = vals*g + g = (vals+1)*g
        s_bidx  = bi;
    }
    __syncthreads();

    if (tid < CH) {
        const int gidx = s_bidx;   // reference uses the raw within-patch index!
        const float g  = x[((size_t)b * N1 + 1 + gidx) * CH + tid];
        out[((size_t)b * (NPATCH + 1) + 1 + p) * CH + tid] = s_scale * g;
    }
}

extern "C" void kernel_launch(void* const* d_in, const int* in_sizes, int n_in,
                              void* d_out, int out_size)
{
    const float* x     = (const float*)d_in[0];  // (4,4097,96) f32
    const float* edge  = (const float*)d_in[1];  // (4,4096,4096) f32
    const float* theta = (const float*)d_in[2];  // (1,96) f32
    float* out = (float*)d_out;                  // (4,1025,96) f32

    node_score_kernel<<<512, 256>>>(x, theta, out);

    // Kernel 2 with programmatic dependent launch: its blocks place on free
    // SMs while kernel 1 runs, prefetch edge, then sync on g_v.
    cudaLaunchConfig_t cfg = {};
    cfg.gridDim  = dim3(BATCH * NPATCH);
    cfg.blockDim = dim3(256);
    cfg.dynamicSmemBytes = 0;
    cfg.stream = 0;
    cudaLaunchAttribute attrs[1];
    attrs[0].id = cudaLaunchAttributeProgrammaticStreamSerialization;
    attrs[0].val.programmaticStreamSerializationAllowed = 1;
    cfg.attrs = attrs;
    cfg.numAttrs = 1;
    cudaLaunchKernelEx(&cfg, score_pool_kernel, edge, x, (float*)d_out);
}

// round 12
// speedup vs baseline: 1.0006x; 1.0006x over previous
#include <cuda_runtime.h>
#include <cstdint>

// Problem constants (fixed shapes per reference)
#define BATCH 4
#define NNODES 4096          // N
#define CH 96                // C
#define N1 (NNODES + 1)      // 4097
#define PS 4                 // pooling_patch_size
#define NPATCH (NNODES / PS) // 1024
// tk = ps / reduction_ratio = 1

// Scratch: v[b][m] = sum_c sigmoid(nodes[b,m,c]) * theta[c]
__device__ float g_v[BATCH * NNODES];

__device__ __forceinline__ float fsig(float x) {
    // fast sigmoid: ~1e-7 rel err (EX2 + RCP on MUFU)
    return __fdividef(1.0f, 1.0f + __expf(-x));
}

// Kernel 1: v[b,m] = dot(sigmoid(x[b,1+m,:]), theta)  (one warp per row).
// 4096 blocks x 128 threads — this exact shape measured the best total
// (finest-granularity drain into kernel 2's placement). Also copies CLS rows.
__global__ __launch_bounds__(128) void node_score_kernel(
    const float* __restrict__ x, const float* __restrict__ theta,
    float* __restrict__ out)
{
    const int g    = blockIdx.x * 4 + (threadIdx.x >> 5);  // row id 0..16383
    const int lane = threadIdx.x & 31;
    const int b = g >> 12;
    const int m = g & (NNODES - 1);

    const float* xr = x + ((size_t)b * N1 + 1 + m) * CH;
    float s = 0.0f;
#pragma unroll
    for (int k = 0; k < 3; k++) {
        const int c = lane + 32 * k;
        s += fsig(xr[c]) * theta[c];
    }
#pragma unroll
    for (int off = 16; off > 0; off >>= 1)
        s += __shfl_down_sync(0xffffffffu, s, off);
    if (lane == 0) g_v[g] = s;

    // CLS row copy: 4*96 = 384 elements, handled by the first 3 blocks
    const int idx = blockIdx.x * 128 + threadIdx.x;
    if (idx < BATCH * CH) {
        const int bb = idx / CH, c = idx % CH;
        out[(size_t)bb * (NPATCH + 1) * CH + c] = x[(size_t)bb * N1 * CH + c];
    }
}

// Kernel 2 (empirically at the chip's effective HBM/LTS ceiling: 268 MB at
// 6.08 TB/s = 98% of ~6.3 TB/s measured cap; occupancy/MUFU/streaming/
// linearization/persistent variants all regressed — locked):
// per patch (b,p): scores for 4 rows = sum_m sigmoid(edge[b,row,m])*v[b,m],
// top-1 (first-index tie-break, matching jax top_k). NOTE: the reference
// gathers nodes[b, idx] where idx is the WITHIN-PATCH offset (0..3), not the
// absolute node index — reproduce that exactly.
__global__ __launch_bounds__(256) void score_pool_kernel(
    const float* __restrict__ edge, const float* __restrict__ x,
    float* __restrict__ out)
{
    __shared__ float red[8][4];
    __shared__ float s_scale;
    __shared__ int   s_bidx;

    const int pg = blockIdx.x;         // 0..4095
    const int b  = pg >> 10;
    const int p  = pg & (NPATCH - 1);
    const int tid  = threadIdx.x;
    const int lane = tid & 31;
    const int wid  = tid >> 5;

    const float4* vv4 = (const float4*)(g_v + (b << 12));
    const float4* e0  = (const float4*)(edge + ((size_t)(b << 12) + (p << 2)) * NNODES);
    // row stride in float4 units: 4096/4 = 1024

    float s0 = 0.f, s1 = 0.f, s2 = 0.f, s3 = 0.f;
#pragma unroll
    for (int i = tid; i < 1024; i += 256) {
        const float4 w  = vv4[i];
        const float4 a0 = e0[i];
        const float4 a1 = e0[i + 1024];
        const float4 a2 = e0[i + 2048];
        const float4 a3 = e0[i + 3072];
        s0 += fsig(a0.x)*w.x + fsig(a0.y)*w.y + fsig(a0.z)*w.z + fsig(a0.w)*w.w;
        s1 += fsig(a1.x)*w.x + fsig(a1.y)*w.y + fsig(a1.z)*w.z + fsig(a1.w)*w.w;
        s2 += fsig(a2.x)*w.x + fsig(a2.y)*w.y + fsig(a2.z)*w.z + fsig(a2.w)*w.w;
        s3 += fsig(a3.x)*w.x + fsig(a3.y)*w.y + fsig(a3.z)*w.z + fsig(a3.w)*w.w;
    }

#pragma unroll
    for (int off = 16; off > 0; off >>= 1) {
        s0 += __shfl_down_sync(0xffffffffu, s0, off);
        s1 += __shfl_down_sync(0xffffffffu, s1, off);
        s2 += __shfl_down_sync(0xffffffffu, s2, off);
        s3 += __shfl_down_sync(0xffffffffu, s3, off);
    }
    if (lane == 0) {
        red[wid][0] = s0; red[wid][1] = s1; red[wid][2] = s2; red[wid][3] = s3;
    }
    __syncthreads();

    if (tid == 0) {
        float sc[4];
#pragma unroll
        for (int r = 0; r < 4; r++) {
            float t = 0.f;
#pragma unroll
            for (int w = 0; w < 8; w++) t += red[w][r];
            sc[r] = t;
        }
        // top-1 with lowest-index tie-break (strict >)
        float best = sc[0]; int bi = 0;
#pragma unroll
        for (int r = 1; r < 4; r++)
            if (sc[r] > best) { best = sc[r]; bi = r; }
        s_scale = best + 1.0f;   // pooled = vals*g + g = (vals+1)*g
        s_bidx  = bi;
    }
    __syncthreads();

    if (tid < CH) {
        const int gidx = s_bidx;   // reference uses the raw within-patch index!
        const float g  = x[((size_t)b * N1 + 1 + gidx) * CH + tid];
        out[((size_t)b * (NPATCH + 1) + 1 + p) * CH + tid] = s_scale * g;
    }
}

extern "C" void kernel_launch(void* const* d_in, const int* in_sizes, int n_in,
                              void* d_out, int out_size)
{
    const float* x     = (const float*)d_in[0];  // (4,4097,96) f32
    const float* edge  = (const float*)d_in[1];  // (4,4096,4096) f32
    const float* theta = (const float*)d_in[2];  // (1,96) f32
    float* out = (float*)d_out;                  // (4,1025,96) f32

    node_score_kernel<<<BATCH * NNODES / 4, 128>>>(x, theta, out);
    score_pool_kernel<<<BATCH * NPATCH, 256>>>(edge, x, out);
}

// round 13
// speedup vs baseline: 1.0052x; 1.0045x over previous
#include <cuda_runtime.h>
#include <cstdint>

// Problem constants (fixed shapes per reference)
#define BATCH 4
#define NNODES 4096          // N
#define CH 96                // C
#define N1 (NNODES + 1)      // 4097
#define PS 4                 // pooling_patch_size
#define NPATCH (NNODES / PS) // 1024
// tk = ps / reduction_ratio = 1

// Scratch: v[b][m] = sum_c sigmoid(nodes[b,m,c]) * theta[c]
__device__ float g_v[BATCH * NNODES];

__device__ __forceinline__ float fsig(float x) {
    // fast sigmoid: ~1e-7 rel err (EX2 + RCP on MUFU)
    return __fdividef(1.0f, 1.0f + __expf(-x));
}

// Kernel 1: v[b,m] = dot(sigmoid(x[b,1+m,:]), theta)  (one warp per row).
// 4096 blocks x 128 threads — best-measured shape. Also copies CLS rows.
__global__ __launch_bounds__(128) void node_score_kernel(
    const float* __restrict__ x, const float* __restrict__ theta,
    float* __restrict__ out)
{
    const int g    = blockIdx.x * 4 + (threadIdx.x >> 5);  // row id 0..16383
    const int lane = threadIdx.x & 31;
    const int b = g >> 12;
    const int m = g & (NNODES - 1);

    const float* xr = x + ((size_t)b * N1 + 1 + m) * CH;
    float s = 0.0f;
#pragma unroll
    for (int k = 0; k < 3; k++) {
        const int c = lane + 32 * k;
        s += fsig(xr[c]) * theta[c];
    }
#pragma unroll
    for (int off = 16; off > 0; off >>= 1)
        s += __shfl_down_sync(0xffffffffu, s, off);
    if (lane == 0) g_v[g] = s;

    // CLS row copy: 4*96 = 384 elements, handled by the first 3 blocks
    const int idx = blockIdx.x * 128 + threadIdx.x;
    if (idx < BATCH * CH) {
        const int bb = idx / CH, c = idx % CH;
        out[(size_t)bb * (NPATCH + 1) * CH + c] = x[(size_t)bb * N1 * CH + c];
    }
}

// Kernel 2: per patch (b,p): scores for 4 rows = sum_m sigmoid(edge[b,row,m])*v[b,m],
// top-1 (first-index tie-break, matching jax top_k). Reference quirk: gathered
// node index is the WITHIN-PATCH offset (0..3), not the absolute node index.
//
// R13 variant: explicit 2-stage software pipeline — batch k+1's loads issue
// before batch k is consumed, doubling per-warp MLP (5 -> 10 in-flight float4).
__global__ __launch_bounds__(256) void score_pool_kernel(
    const float* __restrict__ edge, const float* __restrict__ x,
    float* __restrict__ out)
{
    __shared__ float red[8][4];
    __shared__ float s_scale;
    __shared__ int   s_bidx;

    const int pg = blockIdx.x;         // 0..4095
    const int b  = pg >> 10;
    const int p  = pg & (NPATCH - 1);
    const int tid  = threadIdx.x;
    const int lane = tid & 31;
    const int wid  = tid >> 5;

    const float4* vv4 = (const float4*)(g_v + (b << 12));
    const float4* e0  = (const float4*)(edge + ((size_t)(b << 12) + (p << 2)) * NNODES);
    // row stride in float4 units: 4096/4 = 1024

    float s0 = 0.f, s1 = 0.f, s2 = 0.f, s3 = 0.f;

    // Stage-0 loads
    float4 w  = vv4[tid];
    float4 a0 = e0[tid];
    float4 a1 = e0[tid + 1024];
    float4 a2 = e0[tid + 2048];
    float4 a3 = e0[tid + 3072];

#pragma unroll
    for (int k = 0; k < 4; k++) {
        // Prefetch stage k+1 BEFORE consuming stage k (MLP = 10 float4)
        float4 wn, b0, b1, b2, b3;
        if (k < 3) {
            const int i = tid + 256 * (k + 1);
            wn = vv4[i];
            b0 = e0[i];
            b1 = e0[i + 1024];
            b2 = e0[i + 2048];
            b3 = e0[i + 3072];
        }
        s0 += fsig(a0.x)*w.x + fsig(a0.y)*w.y + fsig(a0.z)*w.z + fsig(a0.w)*w.w;
        s1 += fsig(a1.x)*w.x + fsig(a1.y)*w.y + fsig(a1.z)*w.z + fsig(a1.w)*w.w;
        s2 += fsig(a2.x)*w.x + fsig(a2.y)*w.y + fsig(a2.z)*w.z + fsig(a2.w)*w.w;
        s3 += fsig(a3.x)*w.x + fsig(a3.y)*w.y + fsig(a3.z)*w.z + fsig(a3.w)*w.w;
        if (k < 3) {
            w = wn; a0 = b0; a1 = b1; a2 = b2; a3 = b3;
        }
    }

#pragma unroll
    for (int off = 16; off > 0; off >>= 1) {
        s0 += __shfl_down_sync(0xffffffffu, s0, off);
        s1 += __shfl_down_sync(0xffffffffu, s1, off);
        s2 += __shfl_down_sync(0xffffffffu, s2, off);
        s3 += __shfl_down_sync(0xffffffffu, s3, off);
    }
    if (lane == 0) {
        red[wid][0] = s0; red[wid][1] = s1; red[wid][2] = s2; red[wid][3] = s3;
    }
    __syncthreads();

    if (tid == 0) {
        float sc[4];
#pragma unroll
        for (int r = 0; r < 4; r++) {
            float t = 0.f;
#pragma unroll
            for (int wgi = 0; wgi < 8; wgi++) t += red[wgi][r];
            sc[r] = t;
        }
        // top-1 with lowest-index tie-break (strict >)
        float best = sc[0]; int bi = 0;
#pragma unroll
        for (int r = 1; r < 4; r++)
            if (sc[r] > best) { best = sc[r]; bi = r; }
        s_scale = best + 1.0f;   // pooled = vals*g + g = (vals+1)*g
        s_bidx  = bi;
    }
    __syncthreads();

    if (tid < CH) {
        const int gidx = s_bidx;   // reference uses the raw within-patch index!
        const float g  = x[((size_t)b * N1 + 1 + gidx) * CH + tid];
        out[((size_t)b * (NPATCH + 1) + 1 + p) * CH + tid] = s_scale * g;
    }
}

extern "C" void kernel_launch(void* const* d_in, const int* in_sizes, int n_in,
                              void* d_out, int out_size)
{
    const float* x     = (const float*)d_in[0];  // (4,4097,96) f32
    const float* edge  = (const float*)d_in[1];  // (4,4096,4096) f32
    const float* theta = (const float*)d_in[2];  // (1,96) f32
    float* out = (float*)d_out;                  // (4,1025,96) f32

    node_score_kernel<<<BATCH * NNODES / 4, 128>>>(x, theta, out);
    score_pool_kernel<<<BATCH * NPATCH, 256>>>(edge, x, out);
}